// round 5
// baseline (speedup 1.0000x reference)
#include <cuda_runtime.h>
#include <cuda_bf16.h>
#include <cstdint>

static constexpr int D = 128;       // feature dim == hidden dim
static constexpr int MAXN = 100000;
static constexpr int MAXE = 600000;

// combined MLP input: (1+eps)*x + neighbor sums (written once by gather)
__device__ float g_acc[(size_t)MAXN * D];
// CSR scratch
__device__ int   g_deg[MAXN];
__device__ int   g_rowptr[MAXN];
__device__ int   g_cursor[MAXN];
__device__ int   g_bsum[128];
__device__ int   g_boff[128];
__device__ uint2 g_adj[2 * MAXE];   // (other_node, edge_id)
// pre-split, transposed bf16 weights: [n][k] row-major, 128x128 each
__device__ __align__(16) __nv_bfloat16 g_w1hi[16384];
__device__ __align__(16) __nv_bfloat16 g_w1lo[16384];
__device__ __align__(16) __nv_bfloat16 g_w2hi[16384];
__device__ __align__(16) __nv_bfloat16 g_w2lo[16384];

// ---------------------------------------------------------------------------
// helpers
// ---------------------------------------------------------------------------
__device__ __forceinline__ uint32_t smem_to_u32(const void* p) {
    uint32_t a;
    asm("{ .reg .u64 t; cvta.to.shared.u64 t, %1; cvt.u32.u64 %0, t; }"
        : "=r"(a) : "l"(p));
    return a;
}
__device__ __forceinline__ void ldsm4(uint32_t r[4], uint32_t addr) {
    asm volatile("ldmatrix.sync.aligned.m8n8.x4.shared.b16 {%0,%1,%2,%3}, [%4];"
                 : "=r"(r[0]), "=r"(r[1]), "=r"(r[2]), "=r"(r[3]) : "r"(addr));
}
__device__ __forceinline__ void mma16816(float c[4], const uint32_t a[4],
                                         uint32_t b0, uint32_t b1) {
    asm volatile("mma.sync.aligned.m16n8k16.row.col.f32.bf16.bf16.f32 "
                 "{%0,%1,%2,%3}, {%4,%5,%6,%7}, {%8,%9}, {%0,%1,%2,%3};"
                 : "+f"(c[0]), "+f"(c[1]), "+f"(c[2]), "+f"(c[3])
                 : "r"(a[0]), "r"(a[1]), "r"(a[2]), "r"(a[3]),
                   "r"(b0), "r"(b1));
}
__device__ __forceinline__ void split2(float v0, float v1,
                                       uint32_t& hp, uint32_t& lp) {
    __nv_bfloat16 h0 = __float2bfloat16(v0);
    __nv_bfloat16 h1 = __float2bfloat16(v1);
    __nv_bfloat16 l0 = __float2bfloat16(v0 - __bfloat162float(h0));
    __nv_bfloat16 l1 = __float2bfloat16(v1 - __bfloat162float(h1));
    hp = (uint32_t)__bfloat16_as_ushort(h0) |
         ((uint32_t)__bfloat16_as_ushort(h1) << 16);
    lp = (uint32_t)__bfloat16_as_ushort(l0) |
         ((uint32_t)__bfloat16_as_ushort(l1) << 16);
}

// ---------------------------------------------------------------------------
// weight prep: W [k][n] f32 -> hi/lo bf16 at [n][k]
// ---------------------------------------------------------------------------
__global__ void prep_kernel(const float* __restrict__ W1,
                            const float* __restrict__ W2) {
    int idx = blockIdx.x * blockDim.x + threadIdx.x;  // 0..32767
    int m = idx >> 14;
    int r = idx & 16383;
    int k = r >> 7, n = r & 127;
    float w = (m ? W2 : W1)[k * 128 + n];
    __nv_bfloat16 h = __float2bfloat16(w);
    __nv_bfloat16 l = __float2bfloat16(w - __bfloat162float(h));
    int e = n * 128 + k;
    if (m) { g_w2hi[e] = h; g_w2lo[e] = l; }
    else   { g_w1hi[e] = h; g_w1lo[e] = l; }
}

// ---------------------------------------------------------------------------
// CSR build: histogram -> scan (3 kernels) -> adjacency fill
// ---------------------------------------------------------------------------
__global__ void hist_kernel(const int* __restrict__ ei, int E2) {
    int i = blockIdx.x * blockDim.x + threadIdx.x;
    if (i < E2) atomicAdd(&g_deg[ei[i]], 1);
}

// block = 256 threads x 4 elems = 1024 per block
__global__ void scan1_kernel(int N) {
    __shared__ int wsum[8];
    int b = blockIdx.x, t = threadIdx.x;
    int lane = t & 31, w = t >> 5;
    int i0 = b * 1024 + t * 4;
    int v[4];
    #pragma unroll
    for (int j = 0; j < 4; j++) v[j] = (i0 + j < N) ? g_deg[i0 + j] : 0;
    int tsum = v[0] + v[1] + v[2] + v[3];
    int s = tsum;
    #pragma unroll
    for (int off = 1; off < 32; off <<= 1) {
        int nbr = __shfl_up_sync(~0u, s, off);
        if (lane >= off) s += nbr;
    }
    if (lane == 31) wsum[w] = s;
    __syncthreads();
    if (w == 0) {
        int ws = (lane < 8) ? wsum[lane] : 0;
        #pragma unroll
        for (int off = 1; off < 8; off <<= 1) {
            int nbr = __shfl_up_sync(~0u, ws, off);
            if (lane >= off) ws += nbr;
        }
        if (lane < 8) wsum[lane] = ws;   // inclusive warp prefix
    }
    __syncthreads();
    int warpbase = (w == 0) ? 0 : wsum[w - 1];
    int excl = warpbase + s - tsum;
    #pragma unroll
    for (int j = 0; j < 4; j++) {
        if (i0 + j < N) g_rowptr[i0 + j] = excl;
        excl += v[j];
    }
    if (t == 255) g_bsum[b] = wsum[7];
}

__global__ void scan2_kernel(int nb) {
    __shared__ int s[128];
    int t = threadIdx.x;
    if (t < nb) s[t] = g_bsum[t];
    __syncthreads();
    if (t == 0) {
        int run = 0;
        for (int i = 0; i < nb; i++) { int x = s[i]; s[i] = run; run += x; }
    }
    __syncthreads();
    if (t < nb) g_boff[t] = s[t];
}

__global__ void scan3_kernel(int N) {
    int i = blockIdx.x * blockDim.x + threadIdx.x;
    if (i < N) {
        int r = g_rowptr[i] + g_boff[i >> 10];
        g_rowptr[i] = r;
        g_cursor[i] = r;
    }
}

__global__ void fill_kernel(const int* __restrict__ ei, int E) {
    int e = blockIdx.x * blockDim.x + threadIdx.x;
    if (e >= E) return;
    int u = ei[e], v = ei[E + e];
    int pu = atomicAdd(&g_cursor[u], 1);
    g_adj[pu] = make_uint2((unsigned)v, (unsigned)e);
    int pv = atomicAdd(&g_cursor[v], 1);
    g_adj[pv] = make_uint2((unsigned)u, (unsigned)e);
}

// ---------------------------------------------------------------------------
// gather: one warp per node, no atomics.
//   acc[n] = (1+eps)*x[n] + sum_{(o,e) in adj[n]} relu(x[o] + ea[e])
// ---------------------------------------------------------------------------
__global__ void __launch_bounds__(256)
gather_kernel(const float* __restrict__ x, const float* __restrict__ ea,
              const float* __restrict__ eps, int N) {
    int gt = blockIdx.x * blockDim.x + threadIdx.x;
    int n = gt >> 5, lane = gt & 31;
    if (n >= N) return;

    float s = 1.0f + *eps;
    float4 xv = reinterpret_cast<const float4*>(x + (size_t)n * D)[lane];
    float4 acc;
    acc.x = s * xv.x; acc.y = s * xv.y; acc.z = s * xv.z; acc.w = s * xv.w;

    int start = g_rowptr[n];
    int deg = g_deg[n];
    uint2 nxt = (deg > 0) ? g_adj[start] : make_uint2(0u, 0u);
    for (int i = 0; i < deg; i++) {
        uint2 cur = nxt;
        if (i + 1 < deg) nxt = g_adj[start + i + 1];
        float4 a = __ldg(reinterpret_cast<const float4*>(
                             ea + (size_t)cur.y * D) + lane);
        float4 xo = __ldg(reinterpret_cast<const float4*>(
                              x + (size_t)cur.x * D) + lane);
        acc.x += fmaxf(xo.x + a.x, 0.0f);
        acc.y += fmaxf(xo.y + a.y, 0.0f);
        acc.z += fmaxf(xo.z + a.z, 0.0f);
        acc.w += fmaxf(xo.w + a.w, 0.0f);
    }
    reinterpret_cast<float4*>(g_acc + (size_t)n * D)[lane] = acc;
}

// ---------------------------------------------------------------------------
// fused MLP on HMMA (bf16 2-term split => ~fp32 accuracy)
// CTA: 256 threads / 8 warps / 128 rows; warp owns rows [16w,16w+16).
// A fragments built directly from g_acc (no A smem). Hidden kept in regs.
// smem: W hi/lo [128][136] only => 2 CTAs/SM.
// ---------------------------------------------------------------------------
static constexpr int RS = 136;                       // row stride (bf16)
static constexpr int SM_WHI = 0;
static constexpr int SM_WLO = SM_WHI + 128 * RS * 2; // 34816
static constexpr int SM_B1  = SM_WLO + 128 * RS * 2; // 69632
static constexpr int SM_B2  = SM_B1 + 512;
static constexpr int SM_TOTAL = SM_B2 + 512;         // 70656 B

__device__ __forceinline__ void copy_w(char* smem, int dst,
                                       const __nv_bfloat16* src, int tid) {
    const uint4* s = reinterpret_cast<const uint4*>(src);
    #pragma unroll
    for (int i = tid; i < 2048; i += 256) {
        int r = i >> 4, c8 = i & 15;
        *reinterpret_cast<uint4*>(smem + dst + (r * RS + c8 * 8) * 2) = s[i];
    }
}

__device__ __forceinline__ void load_split(const float* ap, bool valid, int k,
                                           uint32_t& hp, uint32_t& lp) {
    float v0 = 0.f, v1 = 0.f;
    if (valid) {
        float2 p = *reinterpret_cast<const float2*>(ap + k);
        v0 = p.x; v1 = p.y;
    }
    split2(v0, v1, hp, lp);
}

__global__ void __launch_bounds__(256, 2)
mlp_kernel(const float* __restrict__ b1, const float* __restrict__ b2,
           float* __restrict__ out, int N) {
    extern __shared__ char smem[];
    uint32_t sb = smem_to_u32(smem);
    int tid = threadIdx.x;
    int wid = tid >> 5;
    int lane = tid & 31;
    int row0 = blockIdx.x * 128;

    copy_w(smem, SM_WHI, g_w1hi, tid);
    copy_w(smem, SM_WLO, g_w1lo, tid);
    if (tid < 128) {
        reinterpret_cast<float*>(smem + SM_B1)[tid] = b1[tid];
        reinterpret_cast<float*>(smem + SM_B2)[tid] = b2[tid];
    }
    __syncthreads();

    int m2 = (lane & 3) * 2;
    int g  = lane >> 2;
    int r0 = row0 + wid * 16 + g;
    int r1 = r0 + 8;
    bool val0 = r0 < N, val1 = r1 < N;
    const float* a0p = g_acc + (size_t)r0 * D;
    const float* a1p = g_acc + (size_t)r1 * D;

    int brow = (lane & 7) + ((lane & 16) ? 8 : 0);
    int bcol = (lane & 8) ? 8 : 0;

    float c1[16][4];
    #pragma unroll
    for (int i = 0; i < 16; i++)
        c1[i][0] = c1[i][1] = c1[i][2] = c1[i][3] = 0.f;

    // ---- layer 1: A from gmem, W1 from smem ----
    #pragma unroll 2
    for (int kk = 0; kk < 8; kk++) {
        int k0 = kk * 16 + m2;
        uint32_t ahi[4], alo[4];
        load_split(a0p, val0, k0,     ahi[0], alo[0]);
        load_split(a1p, val1, k0,     ahi[1], alo[1]);
        load_split(a0p, val0, k0 + 8, ahi[2], alo[2]);
        load_split(a1p, val1, k0 + 8, ahi[3], alo[3]);
        #pragma unroll
        for (int nt2 = 0; nt2 < 8; nt2++) {
            uint32_t bAddr = sb + SM_WHI +
                (uint32_t)((nt2 * 16 + brow) * RS + kk * 16 + bcol) * 2;
            uint32_t bhi[4], blo[4];
            ldsm4(bhi, bAddr);
            ldsm4(blo, bAddr + (SM_WLO - SM_WHI));
            mma16816(c1[2 * nt2],     ahi, bhi[0], bhi[1]);
            mma16816(c1[2 * nt2],     ahi, blo[0], blo[1]);
            mma16816(c1[2 * nt2],     alo, bhi[0], bhi[1]);
            mma16816(c1[2 * nt2 + 1], ahi, bhi[2], bhi[3]);
            mma16816(c1[2 * nt2 + 1], ahi, blo[2], blo[3]);
            mma16816(c1[2 * nt2 + 1], alo, bhi[2], bhi[3]);
        }
    }

    // ---- hidden = relu(c1 + b1), re-fragmented in registers ----
    const float* b1s = reinterpret_cast<const float*>(smem + SM_B1);
    uint32_t hh[8][4], hl[8][4];
    #pragma unroll
    for (int j = 0; j < 8; j++) {
        float be0 = b1s[16 * j + m2],     be1 = b1s[16 * j + m2 + 1];
        float bo0 = b1s[16 * j + 8 + m2], bo1 = b1s[16 * j + 8 + m2 + 1];
        split2(fmaxf(c1[2 * j][0] + be0, 0.f),
               fmaxf(c1[2 * j][1] + be1, 0.f), hh[j][0], hl[j][0]);
        split2(fmaxf(c1[2 * j][2] + be0, 0.f),
               fmaxf(c1[2 * j][3] + be1, 0.f), hh[j][1], hl[j][1]);
        split2(fmaxf(c1[2 * j + 1][0] + bo0, 0.f),
               fmaxf(c1[2 * j + 1][1] + bo1, 0.f), hh[j][2], hl[j][2]);
        split2(fmaxf(c1[2 * j + 1][2] + bo0, 0.f),
               fmaxf(c1[2 * j + 1][3] + bo1, 0.f), hh[j][3], hl[j][3]);
    }

    __syncthreads();               // everyone done reading W1
    copy_w(smem, SM_WHI, g_w2hi, tid);
    copy_w(smem, SM_WLO, g_w2lo, tid);
    __syncthreads();

    // ---- layer 2 in two n-halves (c2 = 32 regs) ----
    const float* b2s = reinterpret_cast<const float*>(smem + SM_B2);
    #pragma unroll
    for (int h = 0; h < 2; h++) {
        float c2[8][4];
        #pragma unroll
        for (int i = 0; i < 8; i++)
            c2[i][0] = c2[i][1] = c2[i][2] = c2[i][3] = 0.f;

        #pragma unroll
        for (int kk = 0; kk < 8; kk++) {
            #pragma unroll
            for (int i = 0; i < 4; i++) {
                int nt2 = h * 4 + i;
                uint32_t bAddr = sb + SM_WHI +
                    (uint32_t)((nt2 * 16 + brow) * RS + kk * 16 + bcol) * 2;
                uint32_t bhi[4], blo[4];
                ldsm4(bhi, bAddr);
                ldsm4(blo, bAddr + (SM_WLO - SM_WHI));
                mma16816(c2[2 * i],     hh[kk], bhi[0], bhi[1]);
                mma16816(c2[2 * i],     hh[kk], blo[0], blo[1]);
                mma16816(c2[2 * i],     hl[kk], bhi[0], bhi[1]);
                mma16816(c2[2 * i + 1], hh[kk], bhi[2], bhi[3]);
                mma16816(c2[2 * i + 1], hh[kk], blo[2], blo[3]);
                mma16816(c2[2 * i + 1], hl[kk], bhi[2], bhi[3]);
            }
        }

        #pragma unroll
        for (int nt = 0; nt < 8; nt++) {
            int col = (h * 8 + nt) * 8 + m2;
            float bb0 = b2s[col], bb1 = b2s[col + 1];
            if (val0)
                *reinterpret_cast<float2*>(out + (size_t)r0 * D + col) =
                    make_float2(c2[nt][0] + bb0, c2[nt][1] + bb1);
            if (val1)
                *reinterpret_cast<float2*>(out + (size_t)r1 * D + col) =
                    make_float2(c2[nt][2] + bb0, c2[nt][3] + bb1);
        }
    }
}

// ---------------------------------------------------------------------------
// launch: CSR build -> gather (no atomics on features) -> HMMA MLP
// ---------------------------------------------------------------------------
extern "C" void kernel_launch(void* const* d_in, const int* in_sizes, int n_in,
                              void* d_out, int out_size) {
    const float* x   = (const float*)d_in[0];
    const float* ea  = (const float*)d_in[1];
    const float* W1  = (const float*)d_in[2];
    const float* b1  = (const float*)d_in[3];
    const float* W2  = (const float*)d_in[4];
    const float* b2  = (const float*)d_in[5];
    const float* eps = (const float*)d_in[6];
    const int*   ei  = (const int*)d_in[7];

    int N = in_sizes[0] / D;
    int E = in_sizes[1] / D;

    void* degp = nullptr;
    cudaGetSymbolAddress(&degp, g_deg);
    cudaMemsetAsync(degp, 0, (size_t)N * sizeof(int));

    prep_kernel<<<128, 256>>>(W1, W2);

    int E2 = 2 * E;
    hist_kernel<<<(E2 + 255) / 256, 256>>>(ei, E2);

    int nb = (N + 1023) / 1024;
    scan1_kernel<<<nb, 256>>>(N);
    scan2_kernel<<<1, 128>>>(nb);
    scan3_kernel<<<(N + 255) / 256, 256>>>(N);

    fill_kernel<<<(E + 255) / 256, 256>>>(ei, E);

    long long gthreads = (long long)N * 32;
    gather_kernel<<<(int)((gthreads + 255) / 256), 256>>>(x, ea, eps, N);

    cudaFuncSetAttribute(mlp_kernel,
                         cudaFuncAttributeMaxDynamicSharedMemorySize, SM_TOTAL);
    int nbm = (N + 127) / 128;
    mlp_kernel<<<nbm, 256, SM_TOTAL>>>(b1, b2, (float*)d_out, N);
}

// round 6
// speedup vs baseline: 1.1457x; 1.1457x over previous
#include <cuda_runtime.h>
#include <cuda_bf16.h>
#include <cstdint>

static constexpr int D = 128;       // feature dim == hidden dim
static constexpr int MAXN = 100000;
static constexpr int MAXE = 600000;

// MLP input: (1+eps)*x + neighbor sums (accumulated via red.v4)
__device__ float g_acc[(size_t)MAXN * D];
// CSR (u-side only) scratch
__device__ int   g_deg[MAXN];
__device__ int   g_rowptr[MAXN];
__device__ int   g_cursor[MAXN];
__device__ int   g_bsum[128];
__device__ int   g_boff[128];
__device__ uint2 g_adj[MAXE];       // (v_node, edge_id) grouped by u
// pre-split, transposed bf16 weights: [n][k] row-major, 128x128 each
__device__ __align__(16) __nv_bfloat16 g_w1hi[16384];
__device__ __align__(16) __nv_bfloat16 g_w1lo[16384];
__device__ __align__(16) __nv_bfloat16 g_w2hi[16384];
__device__ __align__(16) __nv_bfloat16 g_w2lo[16384];

// ---------------------------------------------------------------------------
// helpers
// ---------------------------------------------------------------------------
__device__ __forceinline__ uint32_t smem_to_u32(const void* p) {
    uint32_t a;
    asm("{ .reg .u64 t; cvta.to.shared.u64 t, %1; cvt.u32.u64 %0, t; }"
        : "=r"(a) : "l"(p));
    return a;
}
__device__ __forceinline__ void ldsm4(uint32_t r[4], uint32_t addr) {
    asm volatile("ldmatrix.sync.aligned.m8n8.x4.shared.b16 {%0,%1,%2,%3}, [%4];"
                 : "=r"(r[0]), "=r"(r[1]), "=r"(r[2]), "=r"(r[3]) : "r"(addr));
}
__device__ __forceinline__ void mma16816(float c[4], const uint32_t a[4],
                                         uint32_t b0, uint32_t b1) {
    asm volatile("mma.sync.aligned.m16n8k16.row.col.f32.bf16.bf16.f32 "
                 "{%0,%1,%2,%3}, {%4,%5,%6,%7}, {%8,%9}, {%0,%1,%2,%3};"
                 : "+f"(c[0]), "+f"(c[1]), "+f"(c[2]), "+f"(c[3])
                 : "r"(a[0]), "r"(a[1]), "r"(a[2]), "r"(a[3]),
                   "r"(b0), "r"(b1));
}
__device__ __forceinline__ void split2(float v0, float v1,
                                       uint32_t& hp, uint32_t& lp) {
    __nv_bfloat16 h0 = __float2bfloat16(v0);
    __nv_bfloat16 h1 = __float2bfloat16(v1);
    __nv_bfloat16 l0 = __float2bfloat16(v0 - __bfloat162float(h0));
    __nv_bfloat16 l1 = __float2bfloat16(v1 - __bfloat162float(h1));
    hp = (uint32_t)__bfloat16_as_ushort(h0) |
         ((uint32_t)__bfloat16_as_ushort(h1) << 16);
    lp = (uint32_t)__bfloat16_as_ushort(l0) |
         ((uint32_t)__bfloat16_as_ushort(l1) << 16);
}

// ---------------------------------------------------------------------------
// weight prep: W [k][n] f32 -> hi/lo bf16 at [n][k]
// ---------------------------------------------------------------------------
__global__ void prep_kernel(const float* __restrict__ W1,
                            const float* __restrict__ W2) {
    int idx = blockIdx.x * blockDim.x + threadIdx.x;  // 0..32767
    int m = idx >> 14;
    int r = idx & 16383;
    int k = r >> 7, n = r & 127;
    float w = (m ? W2 : W1)[k * 128 + n];
    __nv_bfloat16 h = __float2bfloat16(w);
    __nv_bfloat16 l = __float2bfloat16(w - __bfloat162float(h));
    int e = n * 128 + k;
    if (m) { g_w2hi[e] = h; g_w2lo[e] = l; }
    else   { g_w1hi[e] = h; g_w1lo[e] = l; }
}

// ---------------------------------------------------------------------------
// CSR build over u endpoints only
// ---------------------------------------------------------------------------
__global__ void hist_kernel(const int* __restrict__ ei, int E) {
    int i = blockIdx.x * blockDim.x + threadIdx.x;
    if (i < E) atomicAdd(&g_deg[ei[i]], 1);   // u = ei[0..E)
}

// block = 256 threads x 4 elems = 1024 per block
__global__ void scan1_kernel(int N) {
    __shared__ int wsum[8];
    int b = blockIdx.x, t = threadIdx.x;
    int lane = t & 31, w = t >> 5;
    int i0 = b * 1024 + t * 4;
    int v[4];
    #pragma unroll
    for (int j = 0; j < 4; j++) v[j] = (i0 + j < N) ? g_deg[i0 + j] : 0;
    int tsum = v[0] + v[1] + v[2] + v[3];
    int s = tsum;
    #pragma unroll
    for (int off = 1; off < 32; off <<= 1) {
        int nbr = __shfl_up_sync(~0u, s, off);
        if (lane >= off) s += nbr;
    }
    if (lane == 31) wsum[w] = s;
    __syncthreads();
    if (w == 0) {
        int ws = (lane < 8) ? wsum[lane] : 0;
        #pragma unroll
        for (int off = 1; off < 8; off <<= 1) {
            int nbr = __shfl_up_sync(~0u, ws, off);
            if (lane >= off) ws += nbr;
        }
        if (lane < 8) wsum[lane] = ws;   // inclusive warp prefix
    }
    __syncthreads();
    int warpbase = (w == 0) ? 0 : wsum[w - 1];
    int excl = warpbase + s - tsum;
    #pragma unroll
    for (int j = 0; j < 4; j++) {
        if (i0 + j < N) g_rowptr[i0 + j] = excl;
        excl += v[j];
    }
    if (t == 255) g_bsum[b] = wsum[7];
}

__global__ void scan2_kernel(int nb) {
    __shared__ int s[128];
    int t = threadIdx.x;
    if (t < nb) s[t] = g_bsum[t];
    __syncthreads();
    if (t == 0) {
        int run = 0;
        for (int i = 0; i < nb; i++) { int x = s[i]; s[i] = run; run += x; }
    }
    __syncthreads();
    if (t < nb) g_boff[t] = s[t];
}

__global__ void scan3_kernel(int N) {
    int i = blockIdx.x * blockDim.x + threadIdx.x;
    if (i < N) {
        int r = g_rowptr[i] + g_boff[i >> 10];
        g_rowptr[i] = r;
        g_cursor[i] = r;
    }
}

__global__ void fill_kernel(const int* __restrict__ ei, int E) {
    int e = blockIdx.x * blockDim.x + threadIdx.x;
    if (e >= E) return;
    int u = ei[e], v = ei[E + e];
    int pu = atomicAdd(&g_cursor[u], 1);
    g_adj[pu] = make_uint2((unsigned)v, (unsigned)e);
}

// ---------------------------------------------------------------------------
// hybrid pull/push: one warp per node u.
//   reg += (1+eps)*x[u] + sum_e relu(x[v]+ea[e])   (u-side, registers)
//   red.v4 acc[v] += relu(x[u]+ea[e])              (v-side, atomic)
//   red.v4 acc[u] += reg
// ea read exactly ONCE per edge (streaming). Atomic count halved vs R4.
// ---------------------------------------------------------------------------
__global__ void __launch_bounds__(256)
gather_push_kernel(const float* __restrict__ x, const float* __restrict__ ea,
                   const float* __restrict__ eps, int N) {
    int gt = blockIdx.x * blockDim.x + threadIdx.x;
    int n = gt >> 5, lane = gt & 31;
    if (n >= N) return;

    float s = 1.0f + *eps;
    float4 xu = __ldg(reinterpret_cast<const float4*>(x + (size_t)n * D) + lane);
    float4 acc;
    acc.x = s * xu.x; acc.y = s * xu.y; acc.z = s * xu.z; acc.w = s * xu.w;

    int start = g_rowptr[n];
    int deg = g_deg[n];
    uint2 c0 = (deg > 0) ? g_adj[start]     : make_uint2(0u, 0u);
    uint2 c1 = (deg > 1) ? g_adj[start + 1] : make_uint2(0u, 0u);

    for (int i = 0; i < deg; i++) {
        uint2 cur = c0;
        c0 = c1;
        if (i + 2 < deg) c1 = g_adj[start + i + 2];

        float4 a = __ldcs(reinterpret_cast<const float4*>(
                              ea + (size_t)cur.y * D) + lane);
        float4 xo = __ldg(reinterpret_cast<const float4*>(
                              x + (size_t)cur.x * D) + lane);
        // u-side pull (registers)
        acc.x += fmaxf(xo.x + a.x, 0.0f);
        acc.y += fmaxf(xo.y + a.y, 0.0f);
        acc.z += fmaxf(xo.z + a.z, 0.0f);
        acc.w += fmaxf(xo.w + a.w, 0.0f);
        // v-side push (atomic)
        float4 mv;
        mv.x = fmaxf(xu.x + a.x, 0.0f); mv.y = fmaxf(xu.y + a.y, 0.0f);
        mv.z = fmaxf(xu.z + a.z, 0.0f); mv.w = fmaxf(xu.w + a.w, 0.0f);
        float* pv = g_acc + (size_t)cur.x * D + lane * 4;
        asm volatile("red.global.add.v4.f32 [%0], {%1,%2,%3,%4};"
                     :: "l"(pv), "f"(mv.x), "f"(mv.y), "f"(mv.z), "f"(mv.w)
                     : "memory");
    }

    float* pu = g_acc + (size_t)n * D + lane * 4;
    asm volatile("red.global.add.v4.f32 [%0], {%1,%2,%3,%4};"
                 :: "l"(pu), "f"(acc.x), "f"(acc.y), "f"(acc.z), "f"(acc.w)
                 : "memory");
}

// ---------------------------------------------------------------------------
// fused MLP on HMMA (bf16 2-term split => ~fp32 accuracy)
// CTA: 256 threads / 8 warps / 128 rows; warp owns rows [16w,16w+16).
// A fragments built directly from g_acc (no A smem). Hidden kept in regs.
// smem: W hi/lo [128][136] only => 2 CTAs/SM.
// ---------------------------------------------------------------------------
static constexpr int RS = 136;                       // row stride (bf16)
static constexpr int SM_WHI = 0;
static constexpr int SM_WLO = SM_WHI + 128 * RS * 2; // 34816
static constexpr int SM_B1  = SM_WLO + 128 * RS * 2; // 69632
static constexpr int SM_B2  = SM_B1 + 512;
static constexpr int SM_TOTAL = SM_B2 + 512;         // 70656 B

__device__ __forceinline__ void copy_w(char* smem, int dst,
                                       const __nv_bfloat16* src, int tid) {
    const uint4* s = reinterpret_cast<const uint4*>(src);
    #pragma unroll
    for (int i = tid; i < 2048; i += 256) {
        int r = i >> 4, c8 = i & 15;
        *reinterpret_cast<uint4*>(smem + dst + (r * RS + c8 * 8) * 2) = s[i];
    }
}

__device__ __forceinline__ void load_split(const float* ap, bool valid, int k,
                                           uint32_t& hp, uint32_t& lp) {
    float v0 = 0.f, v1 = 0.f;
    if (valid) {
        float2 p = *reinterpret_cast<const float2*>(ap + k);
        v0 = p.x; v1 = p.y;
    }
    split2(v0, v1, hp, lp);
}

__global__ void __launch_bounds__(256, 2)
mlp_kernel(const float* __restrict__ b1, const float* __restrict__ b2,
           float* __restrict__ out, int N) {
    extern __shared__ char smem[];
    uint32_t sb = smem_to_u32(smem);
    int tid = threadIdx.x;
    int wid = tid >> 5;
    int lane = tid & 31;
    int row0 = blockIdx.x * 128;

    copy_w(smem, SM_WHI, g_w1hi, tid);
    copy_w(smem, SM_WLO, g_w1lo, tid);
    if (tid < 128) {
        reinterpret_cast<float*>(smem + SM_B1)[tid] = b1[tid];
        reinterpret_cast<float*>(smem + SM_B2)[tid] = b2[tid];
    }
    __syncthreads();

    int m2 = (lane & 3) * 2;
    int g  = lane >> 2;
    int r0 = row0 + wid * 16 + g;
    int r1 = r0 + 8;
    bool val0 = r0 < N, val1 = r1 < N;
    const float* a0p = g_acc + (size_t)r0 * D;
    const float* a1p = g_acc + (size_t)r1 * D;

    int brow = (lane & 7) + ((lane & 16) ? 8 : 0);
    int bcol = (lane & 8) ? 8 : 0;

    float c1[16][4];
    #pragma unroll
    for (int i = 0; i < 16; i++)
        c1[i][0] = c1[i][1] = c1[i][2] = c1[i][3] = 0.f;

    // ---- layer 1: A from gmem, W1 from smem ----
    #pragma unroll 2
    for (int kk = 0; kk < 8; kk++) {
        int k0 = kk * 16 + m2;
        uint32_t ahi[4], alo[4];
        load_split(a0p, val0, k0,     ahi[0], alo[0]);
        load_split(a1p, val1, k0,     ahi[1], alo[1]);
        load_split(a0p, val0, k0 + 8, ahi[2], alo[2]);
        load_split(a1p, val1, k0 + 8, ahi[3], alo[3]);
        #pragma unroll
        for (int nt2 = 0; nt2 < 8; nt2++) {
            uint32_t bAddr = sb + SM_WHI +
                (uint32_t)((nt2 * 16 + brow) * RS + kk * 16 + bcol) * 2;
            uint32_t bhi[4], blo[4];
            ldsm4(bhi, bAddr);
            ldsm4(blo, bAddr + (SM_WLO - SM_WHI));
            mma16816(c1[2 * nt2],     ahi, bhi[0], bhi[1]);
            mma16816(c1[2 * nt2],     ahi, blo[0], blo[1]);
            mma16816(c1[2 * nt2],     alo, bhi[0], bhi[1]);
            mma16816(c1[2 * nt2 + 1], ahi, bhi[2], bhi[3]);
            mma16816(c1[2 * nt2 + 1], ahi, blo[2], blo[3]);
            mma16816(c1[2 * nt2 + 1], alo, bhi[2], bhi[3]);
        }
    }

    // ---- hidden = relu(c1 + b1), re-fragmented in registers ----
    const float* b1s = reinterpret_cast<const float*>(smem + SM_B1);
    uint32_t hh[8][4], hl[8][4];
    #pragma unroll
    for (int j = 0; j < 8; j++) {
        float be0 = b1s[16 * j + m2],     be1 = b1s[16 * j + m2 + 1];
        float bo0 = b1s[16 * j + 8 + m2], bo1 = b1s[16 * j + 8 + m2 + 1];
        split2(fmaxf(c1[2 * j][0] + be0, 0.f),
               fmaxf(c1[2 * j][1] + be1, 0.f), hh[j][0], hl[j][0]);
        split2(fmaxf(c1[2 * j][2] + be0, 0.f),
               fmaxf(c1[2 * j][3] + be1, 0.f), hh[j][1], hl[j][1]);
        split2(fmaxf(c1[2 * j + 1][0] + bo0, 0.f),
               fmaxf(c1[2 * j + 1][1] + bo1, 0.f), hh[j][2], hl[j][2]);
        split2(fmaxf(c1[2 * j + 1][2] + bo0, 0.f),
               fmaxf(c1[2 * j + 1][3] + bo1, 0.f), hh[j][3], hl[j][3]);
    }

    __syncthreads();               // everyone done reading W1
    copy_w(smem, SM_WHI, g_w2hi, tid);
    copy_w(smem, SM_WLO, g_w2lo, tid);
    __syncthreads();

    // ---- layer 2 in two n-halves (c2 = 32 regs) ----
    const float* b2s = reinterpret_cast<const float*>(smem + SM_B2);
    #pragma unroll
    for (int h = 0; h < 2; h++) {
        float c2[8][4];
        #pragma unroll
        for (int i = 0; i < 8; i++)
            c2[i][0] = c2[i][1] = c2[i][2] = c2[i][3] = 0.f;

        #pragma unroll
        for (int kk = 0; kk < 8; kk++) {
            #pragma unroll
            for (int i = 0; i < 4; i++) {
                int nt2 = h * 4 + i;
                uint32_t bAddr = sb + SM_WHI +
                    (uint32_t)((nt2 * 16 + brow) * RS + kk * 16 + bcol) * 2;
                uint32_t bhi[4], blo[4];
                ldsm4(bhi, bAddr);
                ldsm4(blo, bAddr + (SM_WLO - SM_WHI));
                mma16816(c2[2 * i],     hh[kk], bhi[0], bhi[1]);
                mma16816(c2[2 * i],     hh[kk], blo[0], blo[1]);
                mma16816(c2[2 * i],     hl[kk], bhi[0], bhi[1]);
                mma16816(c2[2 * i + 1], hh[kk], bhi[2], bhi[3]);
                mma16816(c2[2 * i + 1], hh[kk], blo[2], blo[3]);
                mma16816(c2[2 * i + 1], hl[kk], bhi[2], bhi[3]);
            }
        }

        #pragma unroll
        for (int nt = 0; nt < 8; nt++) {
            int col = (h * 8 + nt) * 8 + m2;
            float bb0 = b2s[col], bb1 = b2s[col + 1];
            if (val0)
                *reinterpret_cast<float2*>(out + (size_t)r0 * D + col) =
                    make_float2(c2[nt][0] + bb0, c2[nt][1] + bb1);
            if (val1)
                *reinterpret_cast<float2*>(out + (size_t)r1 * D + col) =
                    make_float2(c2[nt][2] + bb0, c2[nt][3] + bb1);
        }
    }
}

// ---------------------------------------------------------------------------
// launch: u-CSR build -> hybrid gather/push -> HMMA MLP
// ---------------------------------------------------------------------------
extern "C" void kernel_launch(void* const* d_in, const int* in_sizes, int n_in,
                              void* d_out, int out_size) {
    const float* x   = (const float*)d_in[0];
    const float* ea  = (const float*)d_in[1];
    const float* W1  = (const float*)d_in[2];
    const float* b1  = (const float*)d_in[3];
    const float* W2  = (const float*)d_in[4];
    const float* b2  = (const float*)d_in[5];
    const float* eps = (const float*)d_in[6];
    const int*   ei  = (const int*)d_in[7];

    int N = in_sizes[0] / D;
    int E = in_sizes[1] / D;

    void* degp = nullptr;
    cudaGetSymbolAddress(&degp, g_deg);
    cudaMemsetAsync(degp, 0, (size_t)N * sizeof(int));

    void* accp = nullptr;
    cudaGetSymbolAddress(&accp, g_acc);
    cudaMemsetAsync(accp, 0, (size_t)N * D * sizeof(float));

    prep_kernel<<<128, 256>>>(W1, W2);

    hist_kernel<<<(E + 255) / 256, 256>>>(ei, E);

    int nb = (N + 1023) / 1024;
    scan1_kernel<<<nb, 256>>>(N);
    scan2_kernel<<<1, 128>>>(nb);
    scan3_kernel<<<(N + 255) / 256, 256>>>(N);

    fill_kernel<<<(E + 255) / 256, 256>>>(ei, E);

    long long gthreads = (long long)N * 32;
    gather_push_kernel<<<(int)((gthreads + 255) / 256), 256>>>(x, ea, eps, N);

    cudaFuncSetAttribute(mlp_kernel,
                         cudaFuncAttributeMaxDynamicSharedMemorySize, SM_TOTAL);
    int nbm = (N + 127) / 128;
    mlp_kernel<<<nbm, 256, SM_TOTAL>>>(b1, b2, (float*)d_out, N);
}

// round 8
// speedup vs baseline: 1.2328x; 1.0760x over previous
#include <cuda_runtime.h>
#include <cuda_bf16.h>
#include <cstdint>

static constexpr int D = 128;       // feature dim == hidden dim
static constexpr int MAXN = 100000;

// accumulator: neighbor sums ((1+eps)*x folded into MLP A-load)
__device__ float g_acc[(size_t)MAXN * D];
// pre-split, transposed bf16 weights: [n][k] row-major, 128x128 each
__device__ __align__(16) __nv_bfloat16 g_w1hi[16384];
__device__ __align__(16) __nv_bfloat16 g_w1lo[16384];
__device__ __align__(16) __nv_bfloat16 g_w2hi[16384];
__device__ __align__(16) __nv_bfloat16 g_w2lo[16384];

// ---------------------------------------------------------------------------
// helpers
// ---------------------------------------------------------------------------
__device__ __forceinline__ uint32_t smem_to_u32(const void* p) {
    uint32_t a;
    asm("{ .reg .u64 t; cvta.to.shared.u64 t, %1; cvt.u32.u64 %0, t; }"
        : "=r"(a) : "l"(p));
    return a;
}
__device__ __forceinline__ void ldsm4(uint32_t r[4], uint32_t addr) {
    asm volatile("ldmatrix.sync.aligned.m8n8.x4.shared.b16 {%0,%1,%2,%3}, [%4];"
                 : "=r"(r[0]), "=r"(r[1]), "=r"(r[2]), "=r"(r[3]) : "r"(addr));
}
__device__ __forceinline__ void mma16816(float c[4], const uint32_t a[4],
                                         uint32_t b0, uint32_t b1) {
    asm volatile("mma.sync.aligned.m16n8k16.row.col.f32.bf16.bf16.f32 "
                 "{%0,%1,%2,%3}, {%4,%5,%6,%7}, {%8,%9}, {%0,%1,%2,%3};"
                 : "+f"(c[0]), "+f"(c[1]), "+f"(c[2]), "+f"(c[3])
                 : "r"(a[0]), "r"(a[1]), "r"(a[2]), "r"(a[3]),
                   "r"(b0), "r"(b1));
}
__device__ __forceinline__ void split2(float v0, float v1,
                                       uint32_t& hp, uint32_t& lp) {
    __nv_bfloat16 h0 = __float2bfloat16(v0);
    __nv_bfloat16 h1 = __float2bfloat16(v1);
    __nv_bfloat16 l0 = __float2bfloat16(v0 - __bfloat162float(h0));
    __nv_bfloat16 l1 = __float2bfloat16(v1 - __bfloat162float(h1));
    hp = (uint32_t)__bfloat16_as_ushort(h0) |
         ((uint32_t)__bfloat16_as_ushort(h1) << 16);
    lp = (uint32_t)__bfloat16_as_ushort(l0) |
         ((uint32_t)__bfloat16_as_ushort(l1) << 16);
}
// x row load pinned in L2 via cache-hint policy (evict_last)
__device__ __forceinline__ float4 ldg_keep(const float4* p, uint64_t pol) {
    float4 v;
    asm volatile("ld.global.nc.L2::cache_hint.v4.f32 {%0,%1,%2,%3}, [%4], %5;"
                 : "=f"(v.x), "=f"(v.y), "=f"(v.z), "=f"(v.w)
                 : "l"(p), "l"(pol));
    return v;
}

// ---------------------------------------------------------------------------
// setup: blocks [0,128) split weights; blocks [128,...) zero g_acc
// ---------------------------------------------------------------------------
__global__ void setup_kernel(const float* __restrict__ W1,
                             const float* __restrict__ W2, int nzero4) {
    int b = blockIdx.x, t = threadIdx.x;
    if (b < 128) {
        int idx = b * 256 + t;           // 0..32767
        int m = idx >> 14;
        int r = idx & 16383;
        int k = r >> 7, n = r & 127;
        float w = (m ? W2 : W1)[k * 128 + n];
        __nv_bfloat16 h = __float2bfloat16(w);
        __nv_bfloat16 l = __float2bfloat16(w - __bfloat162float(h));
        int e = n * 128 + k;
        if (m) { g_w2hi[e] = h; g_w2lo[e] = l; }
        else   { g_w1hi[e] = h; g_w1lo[e] = l; }
    } else {
        int i = (b - 128) * 256 + t;
        if (i < nzero4)
            reinterpret_cast<float4*>(g_acc)[i] = make_float4(0.f, 0.f, 0.f, 0.f);
    }
}

// ---------------------------------------------------------------------------
// scatter: one warp per edge, red.global.add.v4.f32 into g_acc
// x pinned via L2 evict_last policy; ea streamed with __ldcs (evict-first)
// ---------------------------------------------------------------------------
__global__ void scatter_kernel(const float* __restrict__ x,
                               const float* __restrict__ ea,
                               const int* __restrict__ ei, int E) {
    int gtid = blockIdx.x * blockDim.x + threadIdx.x;
    int e = gtid >> 5;
    int lane = gtid & 31;
    if (e >= E) return;

    uint64_t pol;
    asm volatile("createpolicy.fractional.L2::evict_last.b64 %0, 1.0;"
                 : "=l"(pol));

    int u = ei[e];
    int v = ei[E + e];

    float4 a  = __ldcs(reinterpret_cast<const float4*>(ea + (size_t)e * D) + lane);
    float4 xu = ldg_keep(reinterpret_cast<const float4*>(x + (size_t)u * D) + lane, pol);
    float4 xv = ldg_keep(reinterpret_cast<const float4*>(x + (size_t)v * D) + lane, pol);

    float4 mu, mv;
    mu.x = fmaxf(xv.x + a.x, 0.0f); mu.y = fmaxf(xv.y + a.y, 0.0f);
    mu.z = fmaxf(xv.z + a.z, 0.0f); mu.w = fmaxf(xv.w + a.w, 0.0f);
    mv.x = fmaxf(xu.x + a.x, 0.0f); mv.y = fmaxf(xu.y + a.y, 0.0f);
    mv.z = fmaxf(xu.z + a.z, 0.0f); mv.w = fmaxf(xu.w + a.w, 0.0f);

    float* pu = g_acc + (size_t)u * D + lane * 4;
    float* pv = g_acc + (size_t)v * D + lane * 4;
    asm volatile("red.global.add.v4.f32 [%0], {%1,%2,%3,%4};"
                 :: "l"(pu), "f"(mu.x), "f"(mu.y), "f"(mu.z), "f"(mu.w) : "memory");
    asm volatile("red.global.add.v4.f32 [%0], {%1,%2,%3,%4};"
                 :: "l"(pv), "f"(mv.x), "f"(mv.y), "f"(mv.z), "f"(mv.w) : "memory");
}

// ---------------------------------------------------------------------------
// fused MLP on HMMA (bf16 2-term split => ~fp32 accuracy)
// CTA: 256 threads / 8 warps / 128 rows; warp owns rows [16w,16w+16).
// A fragments built directly from gmem (no A smem). Hidden kept in regs.
// smem: W hi/lo [128][136] only => 2 CTAs/SM.
// ---------------------------------------------------------------------------
static constexpr int RS = 136;                       // row stride (bf16)
static constexpr int SM_WHI = 0;
static constexpr int SM_WLO = SM_WHI + 128 * RS * 2; // 34816
static constexpr int SM_B1  = SM_WLO + 128 * RS * 2; // 69632
static constexpr int SM_B2  = SM_B1 + 512;
static constexpr int SM_TOTAL = SM_B2 + 512;         // 70656 B

__device__ __forceinline__ void copy_w(char* smem, int dst,
                                       const __nv_bfloat16* src, int tid) {
    const uint4* s = reinterpret_cast<const uint4*>(src);
    #pragma unroll
    for (int i = tid; i < 2048; i += 256) {
        int r = i >> 4, c8 = i & 15;
        *reinterpret_cast<uint4*>(smem + dst + (r * RS + c8 * 8) * 2) = s[i];
    }
}

__device__ __forceinline__ void load_split(const float* ap, const float* xp,
                                           bool valid, int k, float s,
                                           uint32_t& hp, uint32_t& lp) {
    float v0 = 0.f, v1 = 0.f;
    if (valid) {
        float2 pa = *reinterpret_cast<const float2*>(ap + k);
        float2 px = *reinterpret_cast<const float2*>(xp + k);
        v0 = fmaf(s, px.x, pa.x);
        v1 = fmaf(s, px.y, pa.y);
    }
    split2(v0, v1, hp, lp);
}

__global__ void __launch_bounds__(256, 2)
mlp_kernel(const float* __restrict__ x, const float* __restrict__ eps,
           const float* __restrict__ b1, const float* __restrict__ b2,
           float* __restrict__ out, int N) {
    extern __shared__ char smem[];
    uint32_t sb = smem_to_u32(smem);
    int tid = threadIdx.x;
    int wid = tid >> 5;
    int lane = tid & 31;
    int row0 = blockIdx.x * 128;

    copy_w(smem, SM_WHI, g_w1hi, tid);
    copy_w(smem, SM_WLO, g_w1lo, tid);
    if (tid < 128) {
        reinterpret_cast<float*>(smem + SM_B1)[tid] = b1[tid];
        reinterpret_cast<float*>(smem + SM_B2)[tid] = b2[tid];
    }
    __syncthreads();

    int m2 = (lane & 3) * 2;
    int g  = lane >> 2;
    int r0 = row0 + wid * 16 + g;
    int r1 = r0 + 8;
    bool val0 = r0 < N, val1 = r1 < N;
    const float* a0p = g_acc + (size_t)r0 * D;
    const float* a1p = g_acc + (size_t)r1 * D;
    const float* x0p = x + (size_t)r0 * D;
    const float* x1p = x + (size_t)r1 * D;
    float s = 1.0f + eps[0];

    int brow = (lane & 7) + ((lane & 16) ? 8 : 0);
    int bcol = (lane & 8) ? 8 : 0;

    float c1[16][4];
    #pragma unroll
    for (int i = 0; i < 16; i++)
        c1[i][0] = c1[i][1] = c1[i][2] = c1[i][3] = 0.f;

    // ---- layer 1: A from gmem, W1 from smem ----
    #pragma unroll 2
    for (int kk = 0; kk < 8; kk++) {
        int k0 = kk * 16 + m2;
        uint32_t ahi[4], alo[4];
        load_split(a0p, x0p, val0, k0,     s, ahi[0], alo[0]);
        load_split(a1p, x1p, val1, k0,     s, ahi[1], alo[1]);
        load_split(a0p, x0p, val0, k0 + 8, s, ahi[2], alo[2]);
        load_split(a1p, x1p, val1, k0 + 8, s, ahi[3], alo[3]);
        #pragma unroll
        for (int nt2 = 0; nt2 < 8; nt2++) {
            uint32_t bAddr = sb + SM_WHI +
                (uint32_t)((nt2 * 16 + brow) * RS + kk * 16 + bcol) * 2;
            uint32_t bhi[4], blo[4];
            ldsm4(bhi, bAddr);
            ldsm4(blo, bAddr + (SM_WLO - SM_WHI));
            mma16816(c1[2 * nt2],     ahi, bhi[0], bhi[1]);
            mma16816(c1[2 * nt2],     ahi, blo[0], blo[1]);
            mma16816(c1[2 * nt2],     alo, bhi[0], bhi[1]);
            mma16816(c1[2 * nt2 + 1], ahi, bhi[2], bhi[3]);
            mma16816(c1[2 * nt2 + 1], ahi, blo[2], blo[3]);
            mma16816(c1[2 * nt2 + 1], alo, bhi[2], bhi[3]);
        }
    }

    // ---- hidden = relu(c1 + b1), re-fragmented in registers ----
    const float* b1s = reinterpret_cast<const float*>(smem + SM_B1);
    uint32_t hh[8][4], hl[8][4];
    #pragma unroll
    for (int j = 0; j < 8; j++) {
        float be0 = b1s[16 * j + m2],     be1 = b1s[16 * j + m2 + 1];
        float bo0 = b1s[16 * j + 8 + m2], bo1 = b1s[16 * j + 8 + m2 + 1];
        split2(fmaxf(c1[2 * j][0] + be0, 0.f),
               fmaxf(c1[2 * j][1] + be1, 0.f), hh[j][0], hl[j][0]);
        split2(fmaxf(c1[2 * j][2] + be0, 0.f),
               fmaxf(c1[2 * j][3] + be1, 0.f), hh[j][1], hl[j][1]);
        split2(fmaxf(c1[2 * j + 1][0] + bo0, 0.f),
               fmaxf(c1[2 * j + 1][1] + bo1, 0.f), hh[j][2], hl[j][2]);
        split2(fmaxf(c1[2 * j + 1][2] + bo0, 0.f),
               fmaxf(c1[2 * j + 1][3] + bo1, 0.f), hh[j][3], hl[j][3]);
    }

    __syncthreads();               // everyone done reading W1
    copy_w(smem, SM_WHI, g_w2hi, tid);
    copy_w(smem, SM_WLO, g_w2lo, tid);
    __syncthreads();

    // ---- layer 2 in two n-halves (c2 = 32 regs) ----
    const float* b2s = reinterpret_cast<const float*>(smem + SM_B2);
    #pragma unroll
    for (int h = 0; h < 2; h++) {
        float c2[8][4];
        #pragma unroll
        for (int i = 0; i < 8; i++)
            c2[i][0] = c2[i][1] = c2[i][2] = c2[i][3] = 0.f;

        #pragma unroll
        for (int kk = 0; kk < 8; kk++) {
            #pragma unroll
            for (int i = 0; i < 4; i++) {
                int nt2 = h * 4 + i;
                uint32_t bAddr = sb + SM_WHI +
                    (uint32_t)((nt2 * 16 + brow) * RS + kk * 16 + bcol) * 2;
                uint32_t bhi[4], blo[4];
                ldsm4(bhi, bAddr);
                ldsm4(blo, bAddr + (SM_WLO - SM_WHI));
                mma16816(c2[2 * i],     hh[kk], bhi[0], bhi[1]);
                mma16816(c2[2 * i],     hh[kk], blo[0], blo[1]);
                mma16816(c2[2 * i],     hl[kk], bhi[0], bhi[1]);
                mma16816(c2[2 * i + 1], hh[kk], bhi[2], bhi[3]);
                mma16816(c2[2 * i + 1], hh[kk], blo[2], blo[3]);
                mma16816(c2[2 * i + 1], hl[kk], bhi[2], bhi[3]);
            }
        }

        #pragma unroll
        for (int nt = 0; nt < 8; nt++) {
            int col = (h * 8 + nt) * 8 + m2;
            float bb0 = b2s[col], bb1 = b2s[col + 1];
            if (val0)
                *reinterpret_cast<float2*>(out + (size_t)r0 * D + col) =
                    make_float2(c2[nt][0] + bb0, c2[nt][1] + bb1);
            if (val1)
                *reinterpret_cast<float2*>(out + (size_t)r1 * D + col) =
                    make_float2(c2[nt][2] + bb0, c2[nt][3] + bb1);
        }
    }
}

// ---------------------------------------------------------------------------
// launch: setup (prep + zero) -> scatter -> HMMA MLP   (3 launches total)
// ---------------------------------------------------------------------------
extern "C" void kernel_launch(void* const* d_in, const int* in_sizes, int n_in,
                              void* d_out, int out_size) {
    const float* x   = (const float*)d_in[0];
    const float* ea  = (const float*)d_in[1];
    const float* W1  = (const float*)d_in[2];
    const float* b1  = (const float*)d_in[3];
    const float* W2  = (const float*)d_in[4];
    const float* b2  = (const float*)d_in[5];
    const float* eps = (const float*)d_in[6];
    const int*   ei  = (const int*)d_in[7];

    int N = in_sizes[0] / D;
    int E = in_sizes[1] / D;

    int nzero4 = N * D / 4;
    int setup_blocks = 128 + (nzero4 + 255) / 256;
    setup_kernel<<<setup_blocks, 256>>>(W1, W2, nzero4);

    long long scatter_threads = (long long)E * 32;
    scatter_kernel<<<(int)((scatter_threads + 255) / 256), 256>>>(x, ea, ei, E);

    cudaFuncSetAttribute(mlp_kernel,
                         cudaFuncAttributeMaxDynamicSharedMemorySize, SM_TOTAL);
    int nbm = (N + 127) / 128;
    mlp_kernel<<<nbm, 256, SM_TOTAL>>>(x, eps, b1, b2, (float*)d_out, N);
}